// round 1
// baseline (speedup 1.0000x reference)
#include <cuda_runtime.h>
#include <math.h>

// ---------------------------------------------------------------------------
// SkillExpertHead — fp32 SIMT baseline (round 1)
//   B=64, T=256, H=1024, 3H=3072, A=32, V=9
// Pipeline:
//   mean -> pb (per-batch fused bias) -> concat(img,state) -> fuse GEMM(gelu)
//   -> gi GEMM (x@Wih^T+bih) -> 256x gru_step -> adapter GEMM x2 (skill-batched)
//   -> head1 GEMM(gelu) -> head2 (N=32) ; done1 GEMM(gelu) -> done2 (N=1,sigmoid)
// ---------------------------------------------------------------------------

#define Bn   64
#define Tn   256
#define BTn  16384
#define Hn   1024
#define H3n  3072
#define KINn 1056   // img(1024) + state(32)

// scratch (device globals: allocation-free rule)
__device__ float g_tctx[Bn*Hn];
__device__ float g_pb  [Bn*Hn];
__device__ float g_xin [BTn*KINn];
__device__ float g_x1  [BTn*Hn];
__device__ float g_gi  [BTn*H3n];
__device__ float g_h   [BTn*Hn];
__device__ float g_y   [BTn*Hn];
__device__ float g_x2  [BTn*Hn];
__device__ float g_hh  [BTn*Hn];
__device__ float g_dh  [BTn*512];

__device__ __forceinline__ float gelu_f(float x){
    return 0.5f*x*(1.0f + erff(x*0.7071067811865476f));
}
__device__ __forceinline__ float sigm_f(float x){
    return 1.0f/(1.0f + expf(-x));
}

// ---------------------------------------------------------------------------
// txt_ctx mean over LTXT=64 -> g_tctx[b][h]
__global__ void mean_kernel(const float* __restrict__ txt){
    int b = blockIdx.x, h = threadIdx.x;
    const float* p = txt + (size_t)b*64*Hn + h;
    float s = 0.f;
    #pragma unroll 8
    for (int l = 0; l < 64; l++) s += p[(size_t)l*Hn];
    g_tctx[b*Hn + h] = s * (1.0f/64.0f);
}

// per-batch fused bias: pb[b][h] = fuse_b[h] + tctx[b]·W[0:1024] + emb[sk]·W[2080:2144]
__global__ void pb_kernel(const float* __restrict__ emb, const int* __restrict__ skill,
                          const float* __restrict__ W, const float* __restrict__ fb){
    int b = blockIdx.y;
    int h = blockIdx.x*128 + threadIdx.x;
    const float* tc = g_tctx + b*Hn;
    float s = fb[h];
    #pragma unroll 4
    for (int k = 0; k < 1024; k++) s = fmaf(tc[k], W[(size_t)k*Hn + h], s);
    const float* e = emb + skill[b]*64;
    #pragma unroll 4
    for (int k = 0; k < 64; k++)  s = fmaf(e[k], W[(size_t)(2080+k)*Hn + h], s);
    g_pb[b*Hn + h] = s;
}

// concat img(1024) + state(32) -> g_xin[n][1056]
__global__ void concat_kernel(const float* __restrict__ img, const float* __restrict__ st){
    int n = blockIdx.x;
    int t = threadIdx.x;          // 264 threads, one float4 each
    float4 v;
    if (t < 256) v = ((const float4*)(img + (size_t)n*1024))[t];
    else         v = ((const float4*)(st  + (size_t)n*32))[t-256];
    ((float4*)(g_xin + (size_t)n*KINn))[t] = v;
}

// ---------------------------------------------------------------------------
// Generic fp32 tiled GEMM: C[M,N] = act(A[M,K] * B + bias)
//   BL:   0 = B is [K,N] row-major (NN), 1 = B is [N,K] row-major (NT)
//   BIAS: 0 none | 1 bias[n] | 2 per-batch-row table bias[(m/256)*N + n]
//         | 3 skill-batched: B += skill[m/256]*K*N, bias[skill*N + n]
//   ACT:  0 none | 1 gelu(erf)
// 128x128 block tile, BK=16, 256 threads, 8x8 per-thread microtile.
// Requires: M%128==0, N%128==0, K%16==0, lda/ldb%4==0.
template<int BL, int BIAS, int ACT>
__global__ void __launch_bounds__(256) gemm_k(
    const float* __restrict__ A, int lda,
    const float* __restrict__ Bm, int ldb,
    const float* __restrict__ bias,
    const int* __restrict__ skill,
    float* __restrict__ C, int ldc,
    int M, int N, int K)
{
    __shared__ float As[16][132];
    __shared__ float Bs[16][132];
    const int n0 = blockIdx.x*128;
    const int m0 = blockIdx.y*128;
    const int t  = threadIdx.x;

    const float* Bp    = Bm;
    const float* biasP = bias;
    if (BIAS == 3){
        int sid = skill[m0 >> 8];
        Bp    += (size_t)sid * K * N;
        biasP += (size_t)sid * N;
    }

    float acc[8][8];
    #pragma unroll
    for (int i = 0; i < 8; i++)
        #pragma unroll
        for (int j = 0; j < 8; j++) acc[i][j] = 0.f;

    const int ar  = t >> 2;          // 0..63 (row pair ar, ar+64)
    const int ak  = (t & 3) << 2;    // k offset 0/4/8/12
    const int bkr = t >> 5;          // 0..7 (k row pair for NN)
    const int bnc = (t & 31) << 2;   // n offset
    const int tx  = t & 15, ty = t >> 4;

    for (int k0 = 0; k0 < K; k0 += 16){
        float4 a0 = *(const float4*)(A + (size_t)(m0+ar)*lda    + k0 + ak);
        float4 a1 = *(const float4*)(A + (size_t)(m0+ar+64)*lda + k0 + ak);
        As[ak+0][ar]=a0.x; As[ak+1][ar]=a0.y; As[ak+2][ar]=a0.z; As[ak+3][ar]=a0.w;
        As[ak+0][ar+64]=a1.x; As[ak+1][ar+64]=a1.y; As[ak+2][ar+64]=a1.z; As[ak+3][ar+64]=a1.w;
        if (BL == 0){
            float4 b0 = *(const float4*)(Bp + (size_t)(k0+bkr)*ldb   + n0 + bnc);
            float4 b1 = *(const float4*)(Bp + (size_t)(k0+bkr+8)*ldb + n0 + bnc);
            *(float4*)&Bs[bkr][bnc]   = b0;
            *(float4*)&Bs[bkr+8][bnc] = b1;
        } else {
            float4 b0 = *(const float4*)(Bp + (size_t)(n0+ar)*ldb    + k0 + ak);
            float4 b1 = *(const float4*)(Bp + (size_t)(n0+ar+64)*ldb + k0 + ak);
            Bs[ak+0][ar]=b0.x; Bs[ak+1][ar]=b0.y; Bs[ak+2][ar]=b0.z; Bs[ak+3][ar]=b0.w;
            Bs[ak+0][ar+64]=b1.x; Bs[ak+1][ar+64]=b1.y; Bs[ak+2][ar+64]=b1.z; Bs[ak+3][ar+64]=b1.w;
        }
        __syncthreads();
        #pragma unroll
        for (int k = 0; k < 16; k++){
            float a[8], bb[8];
            *(float4*)(a)    = *(const float4*)&As[k][ty*8];
            *(float4*)(a+4)  = *(const float4*)&As[k][ty*8+4];
            *(float4*)(bb)   = *(const float4*)&Bs[k][tx*8];
            *(float4*)(bb+4) = *(const float4*)&Bs[k][tx*8+4];
            #pragma unroll
            for (int i = 0; i < 8; i++)
                #pragma unroll
                for (int j = 0; j < 8; j++) acc[i][j] = fmaf(a[i], bb[j], acc[i][j]);
        }
        __syncthreads();
    }

    float bv[8];
    #pragma unroll
    for (int j = 0; j < 8; j++){
        if (BIAS == 1 || BIAS == 3) bv[j] = biasP[n0 + tx*8 + j];
        else if (BIAS == 2)         bv[j] = bias[(size_t)(m0>>8)*N + n0 + tx*8 + j];
        else                        bv[j] = 0.f;
    }
    #pragma unroll
    for (int i = 0; i < 8; i++){
        int row = m0 + ty*8 + i;
        float v[8];
        #pragma unroll
        for (int j = 0; j < 8; j++){
            float x = acc[i][j] + bv[j];
            v[j] = (ACT == 1) ? gelu_f(x) : x;
        }
        float* Cr = C + (size_t)row*ldc + n0 + tx*8;
        *(float4*)Cr     = make_float4(v[0],v[1],v[2],v[3]);
        *(float4*)(Cr+4) = make_float4(v[4],v[5],v[6],v[7]);
    }
}

// ---------------------------------------------------------------------------
// One GRU timestep. Grid = 128 CTAs, each owns 8 hidden columns (x3 gates).
// Computes gh = h_{t-1} @ Whh^T for its 64x24 slab, fuses gate math, writes h_t.
// Thread map: q=t&31 -> b pair {2q,2q+1}; g=t>>5 -> column c0+g (all 3 gates).
__global__ void __launch_bounds__(256) gru_step(
    const float* __restrict__ Whh, const float* __restrict__ bhh, int t)
{
    __shared__ float sh_h[64][66];   // [k][b], padded for float2 reads
    __shared__ float sh_w[24][64];   // [gate*8 + col][k]
    const int c0  = blockIdx.x << 3;
    const int tid = threadIdx.x;
    const int q = tid & 31, g = tid >> 5;
    const int b0 = q << 1;
    float a00=0,a01=0,a02=0,a10=0,a11=0,a12=0;

    const int lb = tid >> 2;         // b for h-tile load
    const int lk = (tid & 3) << 4;   // k quadrant

    for (int kt = 0; kt < Hn; kt += 64){
        if (t > 0){
            const float* hp = g_h + ((size_t)lb*Tn + (t-1))*Hn + kt + lk;
            #pragma unroll
            for (int j = 0; j < 4; j++){
                float4 v = *(const float4*)(hp + j*4);
                sh_h[lk+j*4+0][lb]=v.x; sh_h[lk+j*4+1][lb]=v.y;
                sh_h[lk+j*4+2][lb]=v.z; sh_h[lk+j*4+3][lb]=v.w;
            }
        } else {
            #pragma unroll
            for (int j = 0; j < 16; j++) sh_h[lk+j][lb] = 0.f;
        }
        #pragma unroll
        for (int i = 0; i < 6; i++){
            int idx = tid + i*256;
            int jj = idx >> 6, k = idx & 63;
            int jrow = (jj >> 3)*Hn + c0 + (jj & 7);
            sh_w[jj][k] = Whh[(size_t)jrow*Hn + kt + k];
        }
        __syncthreads();
        #pragma unroll 16
        for (int k = 0; k < 64; k++){
            float2 hv = *(const float2*)&sh_h[k][b0];
            float w0 = sh_w[g][k], w1 = sh_w[8+g][k], w2 = sh_w[16+g][k];
            a00 = fmaf(hv.x,w0,a00); a01 = fmaf(hv.x,w1,a01); a02 = fmaf(hv.x,w2,a02);
            a10 = fmaf(hv.y,w0,a10); a11 = fmaf(hv.y,w1,a11); a12 = fmaf(hv.y,w2,a12);
        }
        __syncthreads();
    }

    const int c = c0 + g;
    const float br = bhh[c], bz = bhh[Hn+c], bn_ = bhh[2*Hn+c];
    #pragma unroll
    for (int e = 0; e < 2; e++){
        int b = b0 + e;
        float gr = e ? a10 : a00;
        float gz = e ? a11 : a01;
        float gn = e ? a12 : a02;
        const float* gi = g_gi + ((size_t)b*Tn + t)*H3n;
        float r = sigm_f(gi[c]        + gr + br);
        float z = sigm_f(gi[Hn + c]   + gz + bz);
        float n = tanhf (gi[2*Hn + c] + r*(gn + bn_));
        float hp = (t > 0) ? g_h[((size_t)b*Tn + t-1)*Hn + c] : 0.f;
        g_h[((size_t)b*Tn + t)*Hn + c] = (1.f - z)*n + z*hp;
    }
}

// ---------------------------------------------------------------------------
// a = g_hh @ head_W2[1024,32] + head_b2 -> out[n*32+c]
__global__ void __launch_bounds__(256) head2_kernel(
    const float* __restrict__ W2, const float* __restrict__ b2,
    float* __restrict__ out)
{
    __shared__ float sh[8*1024];
    int n0 = blockIdx.x*8;
    const float4* src = (const float4*)(g_hh + (size_t)n0*Hn);
    for (int i = threadIdx.x; i < 2048; i += 256) ((float4*)sh)[i] = src[i];
    __syncthreads();
    int r = threadIdx.x >> 5, c = threadIdx.x & 31;
    const float* hr = sh + r*1024;
    float s = b2[c];
    #pragma unroll 4
    for (int k = 0; k < 1024; k++) s = fmaf(hr[k], W2[k*32 + c], s);
    out[(size_t)(n0 + r)*32 + c] = s;
}

// p = sigmoid(g_dh @ done_W2[512,1] + done_b2) -> out[row]
__global__ void __launch_bounds__(256) done2_kernel(
    const float* __restrict__ W2, const float* __restrict__ b2,
    float* __restrict__ out)
{
    int row  = blockIdx.x*8 + (threadIdx.x >> 5);
    int lane = threadIdx.x & 31;
    const float* d = g_dh + (size_t)row*512;
    float s = 0.f;
    #pragma unroll
    for (int k = 0; k < 16; k++) s = fmaf(d[lane + k*32], W2[lane + k*32], s);
    #pragma unroll
    for (int o = 16; o; o >>= 1) s += __shfl_xor_sync(0xffffffffu, s, o);
    if (lane == 0) out[row] = sigm_f(s + b2[0]);
}

// ---------------------------------------------------------------------------
extern "C" void kernel_launch(void* const* d_in, const int* in_sizes, int n_in,
                              void* d_out, int out_size)
{
    const float* txt   = (const float*)d_in[0];
    const float* img   = (const float*)d_in[1];
    const float* st    = (const float*)d_in[2];
    const int*   skill = (const int*)  d_in[3];
    const float* emb   = (const float*)d_in[4];
    const float* fuseW = (const float*)d_in[5];
    const float* fuseb = (const float*)d_in[6];
    const float* Wih   = (const float*)d_in[7];
    const float* Whh   = (const float*)d_in[8];
    const float* bih   = (const float*)d_in[9];
    const float* bhh   = (const float*)d_in[10];
    const float* adW1  = (const float*)d_in[11];
    const float* adb1  = (const float*)d_in[12];
    const float* adW2  = (const float*)d_in[13];
    const float* adb2  = (const float*)d_in[14];
    const float* hW1   = (const float*)d_in[15];
    const float* hb1   = (const float*)d_in[16];
    const float* hW2   = (const float*)d_in[17];
    const float* hb2   = (const float*)d_in[18];
    const float* dW1   = (const float*)d_in[19];
    const float* db1   = (const float*)d_in[20];
    const float* dW2   = (const float*)d_in[21];
    const float* db2   = (const float*)d_in[22];
    float* out = (float*)d_out;

    float *p_xin, *p_x1, *p_gi, *p_h, *p_y, *p_x2, *p_hh, *p_dh, *p_pb;
    cudaGetSymbolAddress((void**)&p_xin, g_xin);
    cudaGetSymbolAddress((void**)&p_x1,  g_x1);
    cudaGetSymbolAddress((void**)&p_gi,  g_gi);
    cudaGetSymbolAddress((void**)&p_h,   g_h);
    cudaGetSymbolAddress((void**)&p_y,   g_y);
    cudaGetSymbolAddress((void**)&p_x2,  g_x2);
    cudaGetSymbolAddress((void**)&p_hh,  g_hh);
    cudaGetSymbolAddress((void**)&p_dh,  g_dh);
    cudaGetSymbolAddress((void**)&p_pb,  g_pb);

    // 1. per-batch pieces
    mean_kernel<<<64, 1024>>>(txt);
    pb_kernel<<<dim3(8, 64), 128>>>(emb, skill, fuseW, fuseb);
    concat_kernel<<<BTn, 264>>>(img, st);

    // 2. fuse: x1 = gelu(xin @ fuse_W[1024:2080] + pb[b])
    gemm_k<0,2,1><<<dim3(8,128), 256>>>(p_xin, KINn, fuseW + 1024*Hn, Hn,
                                        p_pb, nullptr, p_x1, Hn, BTn, Hn, KINn);
    // 3. GRU input gates: gi = x1 @ Wih^T + bih   (NT)
    gemm_k<1,1,0><<<dim3(24,128), 256>>>(p_x1, Hn, Wih, Hn,
                                         bih, nullptr, p_gi, H3n, BTn, H3n, Hn);
    // 4. GRU recurrence, 256 sequential steps
    for (int t = 0; t < Tn; t++) gru_step<<<128, 256>>>(Whh, bhh, t);

    // 5. skill adapter (per-batch weights)
    gemm_k<0,3,1><<<dim3(8,128), 256>>>(p_h, Hn, adW1, Hn,
                                        adb1, skill, p_y,  Hn, BTn, Hn, Hn);
    gemm_k<0,3,0><<<dim3(8,128), 256>>>(p_y, Hn, adW2, Hn,
                                        adb2, skill, p_x2, Hn, BTn, Hn, Hn);
    // 6. action head
    gemm_k<0,1,1><<<dim3(8,128), 256>>>(p_x2, Hn, hW1, Hn,
                                        hb1, nullptr, p_hh, Hn, BTn, Hn, Hn);
    head2_kernel<<<2048, 256>>>(hW2, hb2, out);
    // 7. done head
    gemm_k<0,1,1><<<dim3(4,128), 256>>>(p_x2, Hn, dW1, 512,
                                        db1, nullptr, p_dh, 512, BTn, 512, Hn);
    done2_kernel<<<2048, 256>>>(dW2, db2, out + (size_t)BTn*32);
}

// round 5
// speedup vs baseline: 1.5239x; 1.5239x over previous
#include <cuda_runtime.h>
#include <math.h>

// ---------------------------------------------------------------------------
// SkillExpertHead — round 5 (re-bench; broker timeouts ate rounds 2-4)
//   - GEMMs: 128x64 tile, 8x4 microtile, double-buffered smem, 1 sync/tile
//   - GRU recurrence: k-split partial GEMM (FFMA-bound) + coalesced gate kernel
// ---------------------------------------------------------------------------

#define Bn   64
#define Tn   256
#define BTn  16384
#define Hn   1024
#define H3n  3072
#define KINn 1056   // img(1024) + state(32)
#define KSPL 8      // GRU k-split

// scratch (device globals: allocation-free rule)
__device__ float g_tctx[Bn*Hn];
__device__ float g_pb  [Bn*Hn];
__device__ float g_xin [BTn*KINn];
__device__ float g_x1  [BTn*Hn];
__device__ float g_gi  [BTn*H3n];
__device__ float g_h   [BTn*Hn];
__device__ float g_y   [BTn*Hn];
__device__ float g_x2  [BTn*Hn];
__device__ float g_hh  [BTn*Hn];
__device__ float g_dh  [BTn*512];
__device__ float g_part[KSPL*Bn*H3n];   // [ks][b][o]

__device__ __forceinline__ float gelu_f(float x){
    return 0.5f*x*(1.0f + erff(x*0.7071067811865476f));
}
__device__ __forceinline__ float sigm_f(float x){
    return 1.0f/(1.0f + expf(-x));
}

// ---------------------------------------------------------------------------
// txt_ctx mean over LTXT=64 -> g_tctx[b][h]
__global__ void mean_kernel(const float* __restrict__ txt){
    int b = blockIdx.x, h = threadIdx.x;
    const float* p = txt + (size_t)b*64*Hn + h;
    float s = 0.f;
    #pragma unroll 8
    for (int l = 0; l < 64; l++) s += p[(size_t)l*Hn];
    g_tctx[b*Hn + h] = s * (1.0f/64.0f);
}

// per-batch fused bias: pb[b][h] = fuse_b[h] + tctx[b]·W[0:1024] + emb[sk]·W[2080:2144]
__global__ void pb_kernel(const float* __restrict__ emb, const int* __restrict__ skill,
                          const float* __restrict__ W, const float* __restrict__ fb){
    int b = blockIdx.y;
    int h = blockIdx.x*128 + threadIdx.x;
    const float* tc = g_tctx + b*Hn;
    float s = fb[h];
    #pragma unroll 4
    for (int k = 0; k < 1024; k++) s = fmaf(tc[k], W[(size_t)k*Hn + h], s);
    const float* e = emb + skill[b]*64;
    #pragma unroll 4
    for (int k = 0; k < 64; k++)  s = fmaf(e[k], W[(size_t)(2080+k)*Hn + h], s);
    g_pb[b*Hn + h] = s;
}

// concat img(1024) + state(32) -> g_xin[n][1056]
__global__ void concat_kernel(const float* __restrict__ img, const float* __restrict__ st){
    int n = blockIdx.x;
    int t = threadIdx.x;          // 264 threads, one float4 each
    float4 v;
    if (t < 256) v = ((const float4*)(img + (size_t)n*1024))[t];
    else         v = ((const float4*)(st  + (size_t)n*32))[t-256];
    ((float4*)(g_xin + (size_t)n*KINn))[t] = v;
}

// ---------------------------------------------------------------------------
// fp32 tiled GEMM, double-buffered: C[M,N] = act(A[M,K] * B + bias)
//   BL:   0 = B is [K,N] (NN), 1 = B is [N,K] (NT)
//   BIAS: 1 bias[n] | 2 per-batch table bias[(m/256)*N+n] | 3 skill-batched
//   ACT:  0 none | 1 gelu(erf)
// Tile 128(m) x 64(n), BK=16, 256 threads, 8x4 per-thread microtile.
// Requires: M%128==0, N%64==0, K%16==0.
template<int BL, int BIAS, int ACT>
__global__ void __launch_bounds__(256) gemm_k(
    const float* __restrict__ A, int lda,
    const float* __restrict__ Bm, int ldb,
    const float* __restrict__ bias,
    const int* __restrict__ skill,
    float* __restrict__ C, int ldc,
    int M, int N, int K)
{
    __shared__ float As[2][16][132];
    __shared__ float Bs[2][16][68];
    const int n0 = blockIdx.x*64;
    const int m0 = blockIdx.y*128;
    const int t  = threadIdx.x;

    const float* Bp    = Bm;
    const float* biasP = bias;
    if (BIAS == 3){
        int sid = skill[m0 >> 8];
        Bp    += (size_t)sid * K * N;
        biasP += (size_t)sid * N;
    }

    float acc[8][4];
    #pragma unroll
    for (int i = 0; i < 8; i++)
        #pragma unroll
        for (int j = 0; j < 4; j++) acc[i][j] = 0.f;

    const int ar  = t >> 1;           // A row 0..127
    const int ak  = (t & 1) << 3;     // k offset 0/8
    const int bkr = t >> 4;           // NN: k row 0..15
    const int bnc = (t & 15) << 2;    // NN: n offset
    const int bnr = t >> 2;           // NT: n row 0..63
    const int bk2 = (t & 3) << 2;     // NT: k offset
    const int tx  = t & 15, ty = t >> 4;

    const float* Arow = A + (size_t)(m0+ar)*lda + ak;

    // prologue: tile 0 -> buffer 0
    {
        float4 a0 = *(const float4*)(Arow);
        float4 a1 = *(const float4*)(Arow + 4);
        As[0][ak+0][ar]=a0.x; As[0][ak+1][ar]=a0.y; As[0][ak+2][ar]=a0.z; As[0][ak+3][ar]=a0.w;
        As[0][ak+4][ar]=a1.x; As[0][ak+5][ar]=a1.y; As[0][ak+6][ar]=a1.z; As[0][ak+7][ar]=a1.w;
        if (BL == 0){
            float4 b0 = *(const float4*)(Bp + (size_t)bkr*ldb + n0 + bnc);
            *(float4*)&Bs[0][bkr][bnc] = b0;
        } else {
            float4 b0 = *(const float4*)(Bp + (size_t)(n0+bnr)*ldb + bk2);
            Bs[0][bk2+0][bnr]=b0.x; Bs[0][bk2+1][bnr]=b0.y;
            Bs[0][bk2+2][bnr]=b0.z; Bs[0][bk2+3][bnr]=b0.w;
        }
    }
    __syncthreads();

    int buf = 0;
    for (int k0 = 0; k0 < K; k0 += 16){
        const bool has = (k0 + 16) < K;
        float4 na0, na1, nb0;
        if (has){
            na0 = *(const float4*)(Arow + k0 + 16);
            na1 = *(const float4*)(Arow + k0 + 20);
            if (BL == 0) nb0 = *(const float4*)(Bp + (size_t)(k0+16+bkr)*ldb + n0 + bnc);
            else         nb0 = *(const float4*)(Bp + (size_t)(n0+bnr)*ldb + k0 + 16 + bk2);
        }
        #pragma unroll
        for (int k = 0; k < 16; k++){
            float a[8], bb[4];
            *(float4*)(a)    = *(const float4*)&As[buf][k][ty*8];
            *(float4*)(a+4)  = *(const float4*)&As[buf][k][ty*8+4];
            *(float4*)(bb)   = *(const float4*)&Bs[buf][k][tx*4];
            #pragma unroll
            for (int i = 0; i < 8; i++)
                #pragma unroll
                for (int j = 0; j < 4; j++) acc[i][j] = fmaf(a[i], bb[j], acc[i][j]);
        }
        if (has){
            const int nb = buf ^ 1;
            As[nb][ak+0][ar]=na0.x; As[nb][ak+1][ar]=na0.y; As[nb][ak+2][ar]=na0.z; As[nb][ak+3][ar]=na0.w;
            As[nb][ak+4][ar]=na1.x; As[nb][ak+5][ar]=na1.y; As[nb][ak+6][ar]=na1.z; As[nb][ak+7][ar]=na1.w;
            if (BL == 0) *(float4*)&Bs[nb][bkr][bnc] = nb0;
            else {
                Bs[nb][bk2+0][bnr]=nb0.x; Bs[nb][bk2+1][bnr]=nb0.y;
                Bs[nb][bk2+2][bnr]=nb0.z; Bs[nb][bk2+3][bnr]=nb0.w;
            }
        }
        __syncthreads();
        buf ^= 1;
    }

    float bv[4];
    #pragma unroll
    for (int j = 0; j < 4; j++){
        if (BIAS == 1 || BIAS == 3) bv[j] = biasP[n0 + tx*4 + j];
        else if (BIAS == 2)         bv[j] = bias[(size_t)(m0>>8)*N + n0 + tx*4 + j];
        else                        bv[j] = 0.f;
    }
    #pragma unroll
    for (int i = 0; i < 8; i++){
        int row = m0 + ty*8 + i;
        float v[4];
        #pragma unroll
        for (int j = 0; j < 4; j++){
            float x = acc[i][j] + bv[j];
            v[j] = (ACT == 1) ? gelu_f(x) : x;
        }
        *(float4*)(C + (size_t)row*ldc + n0 + tx*4) = make_float4(v[0],v[1],v[2],v[3]);
    }
}

// ---------------------------------------------------------------------------
// GRU step, phase 1: partial gh GEMM with k-split.
// grid (48 colgroups, 8 ksplit), 128 threads. CTA: 64b x 64o x 128k slab.
// Microtile 8b x 4o -> 48 B LDS per 32 FFMA (FFMA-bound).
// part[(ks*64+b)*3072 + o] = sum_{k in chunk} h[b][k] * Whh[o][k]
__global__ void __launch_bounds__(128) gru_part(
    const float* __restrict__ Whh, int t)
{
    __shared__ float sh_h[32][68];   // [k][b]
    __shared__ float sh_w[32][68];   // [k][o_local]
    const int c0  = blockIdx.x * 64;     // o base (0..3008)
    const int k0  = blockIdx.y * 128;    // k base
    const int tid = threadIdx.x;
    const int bg  = tid >> 4;            // 0..7  -> b0 = bg*8
    const int cg  = tid & 15;            // 0..15 -> oc = cg*4
    const int lr  = tid >> 1;            // 0..63 load row
    const int lk  = (tid & 1) << 4;      // 0/16

    float acc[8][4];
    #pragma unroll
    for (int i = 0; i < 8; i++)
        #pragma unroll
        for (int j = 0; j < 4; j++) acc[i][j] = 0.f;

    for (int kt = 0; kt < 128; kt += 32){
        if (t > 0){
            const float* hp = g_h + ((size_t)lr*Tn + (t-1))*Hn + k0 + kt + lk;
            #pragma unroll
            for (int j = 0; j < 4; j++){
                float4 v = *(const float4*)(hp + j*4);
                sh_h[lk+j*4+0][lr]=v.x; sh_h[lk+j*4+1][lr]=v.y;
                sh_h[lk+j*4+2][lr]=v.z; sh_h[lk+j*4+3][lr]=v.w;
            }
        } else {
            #pragma unroll
            for (int j = 0; j < 16; j++) sh_h[lk+j][lr] = 0.f;
        }
        {
            const float* wp = Whh + (size_t)(c0+lr)*Hn + k0 + kt + lk;
            #pragma unroll
            for (int j = 0; j < 4; j++){
                float4 v = *(const float4*)(wp + j*4);
                sh_w[lk+j*4+0][lr]=v.x; sh_w[lk+j*4+1][lr]=v.y;
                sh_w[lk+j*4+2][lr]=v.z; sh_w[lk+j*4+3][lr]=v.w;
            }
        }
        __syncthreads();
        #pragma unroll
        for (int k = 0; k < 32; k++){
            float a[8], w[4];
            *(float4*)(a)    = *(const float4*)&sh_h[k][bg*8];
            *(float4*)(a+4)  = *(const float4*)&sh_h[k][bg*8+4];
            *(float4*)(w)    = *(const float4*)&sh_w[k][cg*4];
            #pragma unroll
            for (int i = 0; i < 8; i++)
                #pragma unroll
                for (int j = 0; j < 4; j++) acc[i][j] = fmaf(a[i], w[j], acc[i][j]);
        }
        __syncthreads();
    }

    const int bbase = blockIdx.y * 64 + bg * 8;
    #pragma unroll
    for (int i = 0; i < 8; i++){
        *(float4*)(g_part + (size_t)(bbase + i)*H3n + c0 + cg*4) =
            make_float4(acc[i][0], acc[i][1], acc[i][2], acc[i][3]);
    }
}

// GRU step, phase 2: reduce partials + gate math. One thread per (b,c).
// grid 256 x 256 threads; warps run over consecutive c -> fully coalesced.
__global__ void __launch_bounds__(256) gru_gate(
    const float* __restrict__ bhh, int t)
{
    const int idx = blockIdx.x*256 + threadIdx.x;
    const int b = idx >> 10;
    const int c = idx & 1023;
    float sr = 0.f, sz = 0.f, sn = 0.f;
    #pragma unroll
    for (int ks = 0; ks < KSPL; ks++){
        const float* p = g_part + (size_t)(ks*Bn + b)*H3n;
        sr += p[c]; sz += p[1024 + c]; sn += p[2048 + c];
    }
    const float* gi = g_gi + ((size_t)b*Tn + t)*H3n;
    float r = sigm_f(gi[c]        + sr + bhh[c]);
    float z = sigm_f(gi[1024 + c] + sz + bhh[1024 + c]);
    float n = tanhf (gi[2048 + c] + r*(sn + bhh[2048 + c]));
    float hp = (t > 0) ? g_h[((size_t)b*Tn + t-1)*Hn + c] : 0.f;
    g_h[((size_t)b*Tn + t)*Hn + c] = (1.f - z)*n + z*hp;
}

// ---------------------------------------------------------------------------
// a = g_hh @ head_W2[1024,32] + head_b2 -> out[n*32+c]
__global__ void __launch_bounds__(256) head2_kernel(
    const float* __restrict__ W2, const float* __restrict__ b2,
    float* __restrict__ out)
{
    __shared__ float sh[8*1024];
    int n0 = blockIdx.x*8;
    const float4* src = (const float4*)(g_hh + (size_t)n0*Hn);
    for (int i = threadIdx.x; i < 2048; i += 256) ((float4*)sh)[i] = src[i];
    __syncthreads();
    int r = threadIdx.x >> 5, c = threadIdx.x & 31;
    const float* hr = sh + r*1024;
    float s = b2[c];
    #pragma unroll 4
    for (int k = 0; k < 1024; k++) s = fmaf(hr[k], W2[k*32 + c], s);
    out[(size_t)(n0 + r)*32 + c] = s;
}

// p = sigmoid(g_dh @ done_W2[512,1] + done_b2) -> out[row]
__global__ void __launch_bounds__(256) done2_kernel(
    const float* __restrict__ W2, const float* __restrict__ b2,
    float* __restrict__ out)
{
    int row  = blockIdx.x*8 + (threadIdx.x >> 5);
    int lane = threadIdx.x & 31;
    const float* d = g_dh + (size_t)row*512;
    float s = 0.f;
    #pragma unroll
    for (int k = 0; k < 16; k++) s = fmaf(d[lane + k*32], W2[lane + k*32], s);
    #pragma unroll
    for (int o = 16; o; o >>= 1) s += __shfl_xor_sync(0xffffffffu, s, o);
    if (lane == 0) out[row] = sigm_f(s + b2[0]);
}

// ---------------------------------------------------------------------------
extern "C" void kernel_launch(void* const* d_in, const int* in_sizes, int n_in,
                              void* d_out, int out_size)
{
    const float* txt   = (const float*)d_in[0];
    const float* img   = (const float*)d_in[1];
    const float* st    = (const float*)d_in[2];
    const int*   skill = (const int*)  d_in[3];
    const float* emb   = (const float*)d_in[4];
    const float* fuseW = (const float*)d_in[5];
    const float* fuseb = (const float*)d_in[6];
    const float* Wih   = (const float*)d_in[7];
    const float* Whh   = (const float*)d_in[8];
    const float* bih   = (const float*)d_in[9];
    const float* bhh   = (const float*)d_in[10];
    const float* adW1  = (const float*)d_in[11];
    const float* adb1  = (const float*)d_in[12];
    const float* adW2  = (const float*)d_in[13];
    const float* adb2  = (const float*)d_in[14];
    const float* hW1   = (const float*)d_in[15];
    const float* hb1   = (const float*)d_in[16];
    const float* hW2   = (const float*)d_in[17];
    const float* hb2   = (const float*)d_in[18];
    const float* dW1   = (const float*)d_in[19];
    const float* db1   = (const float*)d_in[20];
    const float* dW2   = (const float*)d_in[21];
    const float* db2   = (const float*)d_in[22];
    float* out = (float*)d_out;

    float *p_xin, *p_x1, *p_gi, *p_h, *p_y, *p_x2, *p_hh, *p_dh, *p_pb;
    cudaGetSymbolAddress((void**)&p_xin, g_xin);
    cudaGetSymbolAddress((void**)&p_x1,  g_x1);
    cudaGetSymbolAddress((void**)&p_gi,  g_gi);
    cudaGetSymbolAddress((void**)&p_h,   g_h);
    cudaGetSymbolAddress((void**)&p_y,   g_y);
    cudaGetSymbolAddress((void**)&p_x2,  g_x2);
    cudaGetSymbolAddress((void**)&p_hh,  g_hh);
    cudaGetSymbolAddress((void**)&p_dh,  g_dh);
    cudaGetSymbolAddress((void**)&p_pb,  g_pb);

    // 1. per-batch pieces
    mean_kernel<<<64, 1024>>>(txt);
    pb_kernel<<<dim3(8, 64), 128>>>(emb, skill, fuseW, fuseb);
    concat_kernel<<<BTn, 264>>>(img, st);

    // 2. fuse: x1 = gelu(xin @ fuse_W[1024:2080] + pb[b])
    gemm_k<0,2,1><<<dim3(16,128), 256>>>(p_xin, KINn, fuseW + 1024*Hn, Hn,
                                         p_pb, nullptr, p_x1, Hn, BTn, Hn, KINn);
    // 3. GRU input gates: gi = x1 @ Wih^T + bih   (NT)
    gemm_k<1,1,0><<<dim3(48,128), 256>>>(p_x1, Hn, Wih, Hn,
                                         bih, nullptr, p_gi, H3n, BTn, H3n, Hn);
    // 4. GRU recurrence, 256 sequential steps (partial GEMM + gate fuse)
    for (int t = 0; t < Tn; t++){
        gru_part<<<dim3(48, KSPL), 128>>>(Whh, t);
        gru_gate<<<256, 256>>>(bhh, t);
    }

    // 5. skill adapter (per-batch weights)
    gemm_k<0,3,1><<<dim3(16,128), 256>>>(p_h, Hn, adW1, Hn,
                                         adb1, skill, p_y,  Hn, BTn, Hn, Hn);
    gemm_k<0,3,0><<<dim3(16,128), 256>>>(p_y, Hn, adW2, Hn,
                                         adb2, skill, p_x2, Hn, BTn, Hn, Hn);
    // 6. action head
    gemm_k<0,1,1><<<dim3(16,128), 256>>>(p_x2, Hn, hW1, Hn,
                                         hb1, nullptr, p_hh, Hn, BTn, Hn, Hn);
    head2_kernel<<<2048, 256>>>(hW2, hb2, out);
    // 7. done head
    gemm_k<0,1,1><<<dim3(8,128), 256>>>(p_x2, Hn, dW1, 512,
                                        db1, nullptr, p_dh, 512, BTn, 512, Hn);
    done2_kernel<<<2048, 256>>>(dW2, db2, out + (size_t)BTn*32);
}

// round 17
// speedup vs baseline: 2.0872x; 1.3696x over previous
#include <cuda_runtime.h>
#include <cuda_bf16.h>
#include <math.h>
#include <cstdint>

// ---------------------------------------------------------------------------
// SkillExpertHead — round 17 (re-bench of R12 HMMA design; broker timeouts)
//   mma.sync (HMMA) split-bf16 GEMMs + fp32 GRU recurrence
//   (tcgen05 unavailable: harness compiles for plain sm_103, not sm_103a)
// ---------------------------------------------------------------------------

#define Bn   64
#define Tn   256
#define BTn  16384
#define Hn   1024
#define H3n  3072
#define KFP  1088   // fuse K padded (1056 -> 1088, mult of 32)
#define KSPL 8      // GRU k-split

// ---------------- scratch (device globals; allocation-free rule) -----------
__device__ float g_tctx[Bn*Hn];
__device__ float g_pb  [Bn*Hn];
__device__ __nv_bfloat16 g_xinH[BTn*KFP], g_xinL[BTn*KFP];
__device__ __nv_bfloat16 g_fwH [Hn*KFP],  g_fwL [Hn*KFP];
__device__ __nv_bfloat16 g_x1H [BTn*Hn],  g_x1L [BTn*Hn];
__device__ __nv_bfloat16 g_wihH[H3n*Hn],  g_wihL[H3n*Hn];
__device__ float g_gi[BTn*H3n];
__device__ float g_h [BTn*Hn];
__device__ __nv_bfloat16 g_hH[BTn*Hn],  g_hL[BTn*Hn];
__device__ __nv_bfloat16 g_aw1H[9*Hn*Hn], g_aw1L[9*Hn*Hn];
__device__ __nv_bfloat16 g_aw2H[9*Hn*Hn], g_aw2L[9*Hn*Hn];
__device__ __nv_bfloat16 g_yH [BTn*Hn],  g_yL [BTn*Hn];
__device__ __nv_bfloat16 g_x2H[BTn*Hn],  g_x2L[BTn*Hn];
__device__ __nv_bfloat16 g_hw1H[Hn*Hn],  g_hw1L[Hn*Hn];
__device__ __nv_bfloat16 g_dw1H[512*Hn], g_dw1L[512*Hn];
__device__ float g_hh[BTn*Hn];
__device__ float g_dh[BTn*512];
__device__ float g_part[KSPL*Bn*H3n];

__device__ __forceinline__ float gelu_f(float x){
    return 0.5f*x*(1.0f + erff(x*0.7071067811865476f));
}
__device__ __forceinline__ float sigm_f(float x){
    return 1.0f/(1.0f + expf(-x));
}
__device__ __forceinline__ uint32_t smem_u32(const void* p){
    uint32_t a;
    asm("{ .reg .u64 t; cvta.to.shared.u64 t, %1; cvt.u32.u64 %0, t; }" : "=r"(a) : "l"(p));
    return a;
}
__device__ __forceinline__ void pack2(float a, float b, uint32_t& ph, uint32_t& pl){
    __nv_bfloat16 ha = __float2bfloat16(a), hb = __float2bfloat16(b);
    __nv_bfloat16 la = __float2bfloat16(a - __bfloat162float(ha));
    __nv_bfloat16 lb = __float2bfloat16(b - __bfloat162float(hb));
    ph = (uint32_t)__bfloat16_as_ushort(ha) | ((uint32_t)__bfloat16_as_ushort(hb) << 16);
    pl = (uint32_t)__bfloat16_as_ushort(la) | ((uint32_t)__bfloat16_as_ushort(lb) << 16);
}

// ---------------- warp-MMA primitives (sm_80+, valid on plain sm_103) -------
__device__ __forceinline__ void ldsm_x4(uint32_t& r0, uint32_t& r1, uint32_t& r2, uint32_t& r3, uint32_t a){
    asm volatile("ldmatrix.sync.aligned.m8n8.x4.shared.b16 {%0,%1,%2,%3}, [%4];"
        : "=r"(r0), "=r"(r1), "=r"(r2), "=r"(r3) : "r"(a));
}
__device__ __forceinline__ void ldsm_x2(uint32_t& r0, uint32_t& r1, uint32_t a){
    asm volatile("ldmatrix.sync.aligned.m8n8.x2.shared.b16 {%0,%1}, [%2];"
        : "=r"(r0), "=r"(r1) : "r"(a));
}
__device__ __forceinline__ void mma16816(float* c, const uint32_t* a, const uint32_t* b){
    asm volatile(
        "mma.sync.aligned.m16n8k16.row.col.f32.bf16.bf16.f32 "
        "{%0,%1,%2,%3}, {%4,%5,%6,%7}, {%8,%9}, {%0,%1,%2,%3};"
        : "+f"(c[0]), "+f"(c[1]), "+f"(c[2]), "+f"(c[3])
        : "r"(a[0]), "r"(a[1]), "r"(a[2]), "r"(a[3]), "r"(b[0]), "r"(b[1]));
}

// ---------------- small prep kernels ---------------------------------------
__global__ void mean_kernel(const float* __restrict__ txt){
    int b = blockIdx.x, h = threadIdx.x;
    const float* p = txt + (size_t)b*64*Hn + h;
    float s = 0.f;
    #pragma unroll 8
    for (int l = 0; l < 64; l++) s += p[(size_t)l*Hn];
    g_tctx[b*Hn + h] = s * (1.0f/64.0f);
}

__global__ void pb_kernel(const float* __restrict__ emb, const int* __restrict__ skill,
                          const float* __restrict__ W, const float* __restrict__ fb){
    int b = blockIdx.y;
    int h = blockIdx.x*128 + threadIdx.x;
    const float* tc = g_tctx + b*Hn;
    float s = fb[h];
    #pragma unroll 4
    for (int k = 0; k < 1024; k++) s = fmaf(tc[k], W[(size_t)k*Hn + h], s);
    const float* e = emb + skill[b]*64;
    #pragma unroll 4
    for (int k = 0; k < 64; k++)  s = fmaf(e[k], W[(size_t)(2080+k)*Hn + h], s);
    g_pb[b*Hn + h] = s;
}

__global__ void conv_xin(const float* __restrict__ img, const float* __restrict__ st){
    int n = blockIdx.x;
    int c = threadIdx.x * 4;          // 272 threads
    float4 x;
    if (c < 1024)      x = *(const float4*)(img + (size_t)n*1024 + c);
    else if (c < 1056) x = *(const float4*)(st  + (size_t)n*32 + (c-1024));
    else               x = make_float4(0.f,0.f,0.f,0.f);
    uint32_t ph0, pl0, ph1, pl1;
    pack2(x.x, x.y, ph0, pl0);
    pack2(x.z, x.w, ph1, pl1);
    ((uint2*)(g_xinH + (size_t)n*KFP))[threadIdx.x] = make_uint2(ph0, ph1);
    ((uint2*)(g_xinL + (size_t)n*KFP))[threadIdx.x] = make_uint2(pl0, pl1);
}

__global__ void conv_split(const float* __restrict__ in, __nv_bfloat16* __restrict__ hi,
                           __nv_bfloat16* __restrict__ lo, int n4){
    int i = blockIdx.x*256 + threadIdx.x;
    if (i >= n4) return;
    float4 v = ((const float4*)in)[i];
    uint32_t ph0, pl0, ph1, pl1;
    pack2(v.x, v.y, ph0, pl0);
    pack2(v.z, v.w, ph1, pl1);
    ((uint2*)hi)[i] = make_uint2(ph0, ph1);
    ((uint2*)lo)[i] = make_uint2(pl0, pl1);
}

// transpose + split: W [K][N] fp32 -> hi/lo [N][Kp] bf16 (rows k>=K zero)
__global__ void conv_wT(const float* __restrict__ W, int K, int N, int Kp,
                        __nv_bfloat16* __restrict__ hi, __nv_bfloat16* __restrict__ lo){
    const float* Wp = W + (size_t)blockIdx.z*K*N;
    __nv_bfloat16* hp = hi + (size_t)blockIdx.z*N*Kp;
    __nv_bfloat16* lp = lo + (size_t)blockIdx.z*N*Kp;
    __shared__ float tb[32][33];
    int kt = blockIdx.x*32, nt = blockIdx.y*32;
    for (int i = threadIdx.y; i < 32; i += 8){
        int k = kt + i, n = nt + threadIdx.x;
        tb[i][threadIdx.x] = (k < K) ? Wp[(size_t)k*N + n] : 0.f;
    }
    __syncthreads();
    for (int i = threadIdx.y; i < 32; i += 8){
        int n = nt + i, k = kt + threadIdx.x;
        float v = tb[threadIdx.x][i];
        __nv_bfloat16 h = __float2bfloat16(v);
        hp[(size_t)n*Kp + k] = h;
        lp[(size_t)n*Kp + k] = __float2bfloat16(v - __bfloat162float(h));
    }
}

// ---------------------------------------------------------------------------
// Warp-MMA split-bf16 GEMM: C[M,N] = act(A @ B^T + bias)
//   A: split bf16 [M][K] hi/lo, B: split bf16 [N][K] hi/lo, K mult of 32
//   CTA tile 128(m) x 64(n), BK=32, 8 warps (4m x 2n), warp tile 32x32.
//   3 HMMA per fragment pair: AhBh + AhBl + AlBh (fp32 accum).
//   smem rows padded to 40 bf16 (80B) -> conflict-free ldmatrix.
//   BIASM: 1 bias[n] | 2 per-batch table bias[(m>>8)*N+n] | 3 skill-batched
//   ACT: 0/1 gelu ; OUTSPLIT: 0 fp32 Cf | 1 split bf16 Ch/Cl
// ---------------------------------------------------------------------------
#define WG_BUF  30720        // per double-buffer: AH 10240 + AL 10240 + BH 5120 + BL 5120
#define WG_SMEM (2*WG_BUF)   // 61440

template<int BIASM, int ACT, int OUTSPLIT>
__global__ void __launch_bounds__(256) wgemm(
    const __nv_bfloat16* __restrict__ Ah, const __nv_bfloat16* __restrict__ Al, int lda,
    const __nv_bfloat16* __restrict__ Bh, const __nv_bfloat16* __restrict__ Bl, int ldb,
    const float* __restrict__ bias, const int* __restrict__ skill,
    float* __restrict__ Cf, __nv_bfloat16* __restrict__ Ch, __nv_bfloat16* __restrict__ Cl,
    int ldc, int N, int K)
{
    extern __shared__ __align__(16) char sm[];
    const int m0 = blockIdx.y * 128;
    const int n0 = blockIdx.x * 64;
    const int tid  = threadIdx.x;
    const int lane = tid & 31;
    const int w    = tid >> 5;
    const int wm   = w & 3;          // 0..3 -> m warp row (32 rows each)
    const int wn   = w >> 2;         // 0..1 -> n warp col (32 cols each)
    const uint32_t sbase = smem_u32(sm);

    const __nv_bfloat16 *pBh = Bh, *pBl = Bl;
    const float* pBias = bias;
    if (BIASM == 3){
        int sid = skill[m0 >> 8];
        size_t wo = (size_t)sid * N * ldb;
        pBh += wo; pBl += wo; pBias += (size_t)sid * N;
    }

    float c[2][4][4];
    #pragma unroll
    for (int i = 0; i < 2; i++)
        #pragma unroll
        for (int j = 0; j < 4; j++)
            #pragma unroll
            for (int q = 0; q < 4; q++) c[i][j][q] = 0.f;

    // load map: A 512 uint4 (2/thread/matrix), B 256 uint4 (1/thread/matrix)
    const int ar0 = tid >> 2;            // 0..63 (i=0), +64 (i=1)
    const int aq  = (tid & 3) << 3;      // k-elem offset 0/8/16/24 -> 16B
    const int br0 = tid >> 2;            // 0..63
    const int bq  = (tid & 3) << 3;

    // prologue: chunk 0 -> buffer 0
    {
        char* s = sm;
        #pragma unroll
        for (int i = 0; i < 2; i++){
            int r = ar0 + i*64;
            uint4 vh = *(const uint4*)(Ah + (size_t)(m0+r)*lda + aq);
            uint4 vl = *(const uint4*)(Al + (size_t)(m0+r)*lda + aq);
            *(uint4*)(s + r*80 + aq*2)         = vh;
            *(uint4*)(s + 10240 + r*80 + aq*2) = vl;
        }
        uint4 bh = *(const uint4*)(pBh + (size_t)(n0+br0)*ldb + bq);
        uint4 bl = *(const uint4*)(pBl + (size_t)(n0+br0)*ldb + bq);
        *(uint4*)(s + 20480 + br0*80 + bq*2) = bh;
        *(uint4*)(s + 25600 + br0*80 + bq*2) = bl;
    }
    __syncthreads();

    int buf = 0;
    for (int kb = 0; kb < K; kb += 32){
        const bool has = (kb + 32) < K;
        uint4 na0, na1, nal0, nal1, nb0, nbl0;
        if (has){
            na0  = *(const uint4*)(Ah + (size_t)(m0+ar0)*lda    + kb + 32 + aq);
            na1  = *(const uint4*)(Ah + (size_t)(m0+ar0+64)*lda + kb + 32 + aq);
            nal0 = *(const uint4*)(Al + (size_t)(m0+ar0)*lda    + kb + 32 + aq);
            nal1 = *(const uint4*)(Al + (size_t)(m0+ar0+64)*lda + kb + 32 + aq);
            nb0  = *(const uint4*)(pBh + (size_t)(n0+br0)*ldb + kb + 32 + bq);
            nbl0 = *(const uint4*)(pBl + (size_t)(n0+br0)*ldb + kb + 32 + bq);
        }

        // compute on current buffer
        const uint32_t base = sbase + buf*WG_BUF;
        const uint32_t AHa = base, ALa = base + 10240;
        const uint32_t BHa = base + 20480, BLa = base + 25600;
        const uint32_t aRow = (uint32_t)((lane & 15) * 80) + ((lane >> 4) << 4);
        const uint32_t bRow = (uint32_t)((lane & 7) * 80) + (((lane >> 3) & 1) << 4);

        #pragma unroll
        for (int ks = 0; ks < 2; ks++){
            const uint32_t ko = ks * 32;   // 16 bf16 = 32 bytes
            uint32_t aH[2][4], aL[2][4], bH[4][2], bL[4][2];
            #pragma unroll
            for (int mi = 0; mi < 2; mi++){
                uint32_t off = (uint32_t)((wm*32 + mi*16) * 80) + ko + aRow;
                ldsm_x4(aH[mi][0], aH[mi][1], aH[mi][2], aH[mi][3], AHa + off);
                ldsm_x4(aL[mi][0], aL[mi][1], aL[mi][2], aL[mi][3], ALa + off);
            }
            #pragma unroll
            for (int ni = 0; ni < 4; ni++){
                uint32_t off = (uint32_t)((wn*32 + ni*8) * 80) + ko + bRow;
                ldsm_x2(bH[ni][0], bH[ni][1], BHa + off);
                ldsm_x2(bL[ni][0], bL[ni][1], BLa + off);
            }
            #pragma unroll
            for (int mi = 0; mi < 2; mi++)
                #pragma unroll
                for (int ni = 0; ni < 4; ni++){
                    mma16816(c[mi][ni], aH[mi], bH[ni]);
                    mma16816(c[mi][ni], aH[mi], bL[ni]);
                    mma16816(c[mi][ni], aL[mi], bH[ni]);
                }
        }

        if (has){
            char* s = sm + (buf ^ 1)*WG_BUF;
            *(uint4*)(s + ar0*80 + aq*2)              = na0;
            *(uint4*)(s + (ar0+64)*80 + aq*2)         = na1;
            *(uint4*)(s + 10240 + ar0*80 + aq*2)      = nal0;
            *(uint4*)(s + 10240 + (ar0+64)*80 + aq*2) = nal1;
            *(uint4*)(s + 20480 + br0*80 + bq*2)      = nb0;
            *(uint4*)(s + 25600 + br0*80 + bq*2)      = nbl0;
        }
        __syncthreads();
        buf ^= 1;
    }

    // epilogue: m16n8 output map: row = lane>>2 (+8), col = (lane&3)*2 (+1)
    const int r0 = lane >> 2, c0 = (lane & 3) * 2;
    const float* brow = (BIASM == 2) ? (bias + (size_t)(m0 >> 8) * N) : pBias;
    #pragma unroll
    for (int mi = 0; mi < 2; mi++){
        int gr = m0 + wm*32 + mi*16 + r0;
        #pragma unroll
        for (int ni = 0; ni < 4; ni++){
            int gc = n0 + wn*32 + ni*8 + c0;
            float b0 = brow[gc], b1 = brow[gc+1];
            float v00 = c[mi][ni][0] + b0, v01 = c[mi][ni][1] + b1;
            float v10 = c[mi][ni][2] + b0, v11 = c[mi][ni][3] + b1;
            if (ACT == 1){ v00 = gelu_f(v00); v01 = gelu_f(v01); v10 = gelu_f(v10); v11 = gelu_f(v11); }
            if (OUTSPLIT){
                uint32_t ph, pl;
                pack2(v00, v01, ph, pl);
                *(uint32_t*)(Ch + (size_t)gr*ldc + gc) = ph;
                *(uint32_t*)(Cl + (size_t)gr*ldc + gc) = pl;
                pack2(v10, v11, ph, pl);
                *(uint32_t*)(Ch + (size_t)(gr+8)*ldc + gc) = ph;
                *(uint32_t*)(Cl + (size_t)(gr+8)*ldc + gc) = pl;
            } else {
                *(float2*)(Cf + (size_t)gr*ldc + gc)     = make_float2(v00, v01);
                *(float2*)(Cf + (size_t)(gr+8)*ldc + gc) = make_float2(v10, v11);
            }
        }
    }
}

// ---------------- GRU recurrence (unchanged from R5 winner) -----------------
__global__ void __launch_bounds__(128) gru_part(
    const float* __restrict__ Whh, int t)
{
    __shared__ float sh_h[32][68];
    __shared__ float sh_w[32][68];
    const int c0  = blockIdx.x * 64;
    const int k0  = blockIdx.y * 128;
    const int tid = threadIdx.x;
    const int bg  = tid >> 4;
    const int cg  = tid & 15;
    const int lr  = tid >> 1;
    const int lk  = (tid & 1) << 4;

    float acc[8][4];
    #pragma unroll
    for (int i = 0; i < 8; i++)
        #pragma unroll
        for (int j = 0; j < 4; j++) acc[i][j] = 0.f;

    for (int kt = 0; kt < 128; kt += 32){
        if (t > 0){
            const float* hp = g_h + ((size_t)lr*Tn + (t-1))*Hn + k0 + kt + lk;
            #pragma unroll
            for (int j = 0; j < 4; j++){
                float4 v = *(const float4*)(hp + j*4);
                sh_h[lk+j*4+0][lr]=v.x; sh_h[lk+j*4+1][lr]=v.y;
                sh_h[lk+j*4+2][lr]=v.z; sh_h[lk+j*4+3][lr]=v.w;
            }
        } else {
            #pragma unroll
            for (int j = 0; j < 16; j++) sh_h[lk+j][lr] = 0.f;
        }
        {
            const float* wp = Whh + (size_t)(c0+lr)*Hn + k0 + kt + lk;
            #pragma unroll
            for (int j = 0; j < 4; j++){
                float4 v = *(const float4*)(wp + j*4);
                sh_w[lk+j*4+0][lr]=v.x; sh_w[lk+j*4+1][lr]=v.y;
                sh_w[lk+j*4+2][lr]=v.z; sh_w[lk+j*4+3][lr]=v.w;
            }
        }
        __syncthreads();
        #pragma unroll
        for (int k = 0; k < 32; k++){
            float a[8], wv[4];
            *(float4*)(a)    = *(const float4*)&sh_h[k][bg*8];
            *(float4*)(a+4)  = *(const float4*)&sh_h[k][bg*8+4];
            *(float4*)(wv)   = *(const float4*)&sh_w[k][cg*4];
            #pragma unroll
            for (int i = 0; i < 8; i++)
                #pragma unroll
                for (int j = 0; j < 4; j++) acc[i][j] = fmaf(a[i], wv[j], acc[i][j]);
        }
        __syncthreads();
    }

    const int bbase = blockIdx.y * 64 + bg * 8;
    #pragma unroll
    for (int i = 0; i < 8; i++){
        *(float4*)(g_part + (size_t)(bbase + i)*H3n + c0 + cg*4) =
            make_float4(acc[i][0], acc[i][1], acc[i][2], acc[i][3]);
    }
}

__global__ void __launch_bounds__(256) gru_gate(
    const float* __restrict__ bhh, int t)
{
    const int idx = blockIdx.x*256 + threadIdx.x;
    const int b = idx >> 10;
    const int c = idx & 1023;
    float sr = 0.f, sz = 0.f, sn = 0.f;
    #pragma unroll
    for (int ks = 0; ks < KSPL; ks++){
        const float* p = g_part + (size_t)(ks*Bn + b)*H3n;
        sr += p[c]; sz += p[1024 + c]; sn += p[2048 + c];
    }
    const float* gi = g_gi + ((size_t)b*Tn + t)*H3n;
    float r = sigm_f(gi[c]        + sr + bhh[c]);
    float z = sigm_f(gi[1024 + c] + sz + bhh[1024 + c]);
    float n = tanhf (gi[2048 + c] + r*(sn + bhh[2048 + c]));
    float hp = (t > 0) ? g_h[((size_t)b*Tn + t-1)*Hn + c] : 0.f;
    g_h[((size_t)b*Tn + t)*Hn + c] = (1.f - z)*n + z*hp;
}

// ---------------- tiny heads ------------------------------------------------
__global__ void __launch_bounds__(256) head2_kernel(
    const float* __restrict__ W2, const float* __restrict__ b2,
    float* __restrict__ out)
{
    __shared__ float sh[8*1024];
    int n0 = blockIdx.x*8;
    const float4* src = (const float4*)(g_hh + (size_t)n0*Hn);
    for (int i = threadIdx.x; i < 2048; i += 256) ((float4*)sh)[i] = src[i];
    __syncthreads();
    int r = threadIdx.x >> 5, c = threadIdx.x & 31;
    const float* hr = sh + r*1024;
    float s = b2[c];
    #pragma unroll 4
    for (int k = 0; k < 1024; k++) s = fmaf(hr[k], W2[k*32 + c], s);
    out[(size_t)(n0 + r)*32 + c] = s;
}

__global__ void __launch_bounds__(256) done2_kernel(
    const float* __restrict__ W2, const float* __restrict__ b2,
    float* __restrict__ out)
{
    int row  = blockIdx.x*8 + (threadIdx.x >> 5);
    int lane = threadIdx.x & 31;
    const float* d = g_dh + (size_t)row*512;
    float s = 0.f;
    #pragma unroll
    for (int k = 0; k < 16; k++) s = fmaf(d[lane + k*32], W2[lane + k*32], s);
    #pragma unroll
    for (int o = 16; o; o >>= 1) s += __shfl_xor_sync(0xffffffffu, s, o);
    if (lane == 0) out[row] = sigm_f(s + b2[0]);
}

// ---------------------------------------------------------------------------
extern "C" void kernel_launch(void* const* d_in, const int* in_sizes, int n_in,
                              void* d_out, int out_size)
{
    const float* txt   = (const float*)d_in[0];
    const float* img   = (const float*)d_in[1];
    const float* st    = (const float*)d_in[2];
    const int*   skill = (const int*)  d_in[3];
    const float* emb   = (const float*)d_in[4];
    const float* fuseW = (const float*)d_in[5];
    const float* fuseb = (const float*)d_in[6];
    const float* Wih   = (const float*)d_in[7];
    const float* Whh   = (const float*)d_in[8];
    const float* bih   = (const float*)d_in[9];
    const float* bhh   = (const float*)d_in[10];
    const float* adW1  = (const float*)d_in[11];
    const float* adb1  = (const float*)d_in[12];
    const float* adW2  = (const float*)d_in[13];
    const float* adb2  = (const float*)d_in[14];
    const float* hW1   = (const float*)d_in[15];
    const float* hb1   = (const float*)d_in[16];
    const float* hW2   = (const float*)d_in[17];
    const float* hb2   = (const float*)d_in[18];
    const float* dW1   = (const float*)d_in[19];
    const float* db1   = (const float*)d_in[20];
    const float* dW2   = (const float*)d_in[21];
    const float* db2   = (const float*)d_in[22];
    float* out = (float*)d_out;

    float *p_gi, *p_h, *p_hh, *p_dh, *p_pb;
    cudaGetSymbolAddress((void**)&p_gi, g_gi);
    cudaGetSymbolAddress((void**)&p_h,  g_h);
    cudaGetSymbolAddress((void**)&p_hh, g_hh);
    cudaGetSymbolAddress((void**)&p_dh, g_dh);
    cudaGetSymbolAddress((void**)&p_pb, g_pb);

    __nv_bfloat16 *xinH,*xinL,*fwH,*fwL,*x1H,*x1L,*wihH,*wihL,*hH,*hL;
    __nv_bfloat16 *aw1H,*aw1L,*aw2H,*aw2L,*yH,*yL,*x2H,*x2L,*hw1H,*hw1L,*dw1H,*dw1L;
    cudaGetSymbolAddress((void**)&xinH, g_xinH); cudaGetSymbolAddress((void**)&xinL, g_xinL);
    cudaGetSymbolAddress((void**)&fwH,  g_fwH);  cudaGetSymbolAddress((void**)&fwL,  g_fwL);
    cudaGetSymbolAddress((void**)&x1H,  g_x1H);  cudaGetSymbolAddress((void**)&x1L,  g_x1L);
    cudaGetSymbolAddress((void**)&wihH, g_wihH); cudaGetSymbolAddress((void**)&wihL, g_wihL);
    cudaGetSymbolAddress((void**)&hH,   g_hH);   cudaGetSymbolAddress((void**)&hL,   g_hL);
    cudaGetSymbolAddress((void**)&aw1H, g_aw1H); cudaGetSymbolAddress((void**)&aw1L, g_aw1L);
    cudaGetSymbolAddress((void**)&aw2H, g_aw2H); cudaGetSymbolAddress((void**)&aw2L, g_aw2L);
    cudaGetSymbolAddress((void**)&yH,   g_yH);   cudaGetSymbolAddress((void**)&yL,   g_yL);
    cudaGetSymbolAddress((void**)&x2H,  g_x2H);  cudaGetSymbolAddress((void**)&x2L,  g_x2L);
    cudaGetSymbolAddress((void**)&hw1H, g_hw1H); cudaGetSymbolAddress((void**)&hw1L, g_hw1L);
    cudaGetSymbolAddress((void**)&dw1H, g_dw1H); cudaGetSymbolAddress((void**)&dw1L, g_dw1L);

    cudaFuncSetAttribute(wgemm<2,1,1>, cudaFuncAttributeMaxDynamicSharedMemorySize, WG_SMEM);
    cudaFuncSetAttribute(wgemm<1,0,0>, cudaFuncAttributeMaxDynamicSharedMemorySize, WG_SMEM);
    cudaFuncSetAttribute(wgemm<3,1,1>, cudaFuncAttributeMaxDynamicSharedMemorySize, WG_SMEM);
    cudaFuncSetAttribute(wgemm<3,0,1>, cudaFuncAttributeMaxDynamicSharedMemorySize, WG_SMEM);
    cudaFuncSetAttribute(wgemm<1,1,0>, cudaFuncAttributeMaxDynamicSharedMemorySize, WG_SMEM);

    // 1. prep + weight conversions
    mean_kernel<<<64, 1024>>>(txt);
    pb_kernel<<<dim3(8, 64), 128>>>(emb, skill, fuseW, fuseb);
    conv_xin<<<BTn, 272>>>(img, st);
    conv_wT<<<dim3(34, 32, 1), dim3(32, 8)>>>(fuseW + 1024*Hn, 1056, 1024, KFP, fwH, fwL);
    conv_split<<<(H3n*Hn/4 + 255)/256, 256>>>(Wih, wihH, wihL, H3n*Hn/4);
    conv_wT<<<dim3(32, 32, 9), dim3(32, 8)>>>(adW1, 1024, 1024, 1024, aw1H, aw1L);
    conv_wT<<<dim3(32, 32, 9), dim3(32, 8)>>>(adW2, 1024, 1024, 1024, aw2H, aw2L);
    conv_wT<<<dim3(32, 32, 1), dim3(32, 8)>>>(hW1, 1024, 1024, 1024, hw1H, hw1L);
    conv_wT<<<dim3(32, 16, 1), dim3(32, 8)>>>(dW1, 1024, 512, 1024, dw1H, dw1L);

    // 2. fuse: x1 = gelu(xin @ fuseW_sub + pb[b])  -> split bf16
    wgemm<2,1,1><<<dim3(16, 128), 256, WG_SMEM>>>(xinH, xinL, KFP, fwH, fwL, KFP,
        p_pb, nullptr, nullptr, x1H, x1L, Hn, Hn, KFP);
    // 3. gi = x1 @ Wih^T + bih  -> fp32
    wgemm<1,0,0><<<dim3(48, 128), 256, WG_SMEM>>>(x1H, x1L, Hn, wihH, wihL, Hn,
        bih, nullptr, p_gi, nullptr, nullptr, H3n, H3n, Hn);
    // 4. GRU recurrence (fp32)
    for (int t = 0; t < Tn; t++){
        gru_part<<<dim3(48, KSPL), 128>>>(Whh, t);
        gru_gate<<<256, 256>>>(bhh, t);
    }
    conv_split<<<(BTn*Hn/4 + 255)/256, 256>>>(p_h, hH, hL, BTn*Hn/4);

    // 5. skill adapter
    wgemm<3,1,1><<<dim3(16, 128), 256, WG_SMEM>>>(hH, hL, Hn, aw1H, aw1L, Hn,
        adb1, skill, nullptr, yH, yL, Hn, Hn, Hn);
    wgemm<3,0,1><<<dim3(16, 128), 256, WG_SMEM>>>(yH, yL, Hn, aw2H, aw2L, Hn,
        adb2, skill, nullptr, x2H, x2L, Hn, Hn, Hn);
    // 6. heads
    wgemm<1,1,0><<<dim3(16, 128), 256, WG_SMEM>>>(x2H, x2L, Hn, hw1H, hw1L, Hn,
        hb1, nullptr, p_hh, nullptr, nullptr, Hn, Hn, Hn);
    head2_kernel<<<2048, 256>>>(hW2, hb2, out);
    wgemm<1,1,0><<<dim3(8, 128), 256, WG_SMEM>>>(x2H, x2L, Hn, dw1H, dw1L, Hn,
        db1, nullptr, p_dh, nullptr, nullptr, 512, 512, Hn);
    done2_kernel<<<2048, 256>>>(dW2, db2, out + (size_t)BTn*32);
}